// round 15
// baseline (speedup 1.0000x reference)
#include <cuda_runtime.h>
#include <cuda_fp16.h>
#include <math.h>
#include <stdint.h>

typedef __half h16;

// Problem constants
#define BB 2
#define SS 2048
#define DD 768
#define HH 12
#define FF 3072
#define HDD 64
#define ROWS (BB*SS)          // 4096
#define BH (BB*HH)            // 24

// -------------------- device scratch (single fp16 activations) --------------------
__device__ __align__(16) h16  g_hx  [ROWS*DD];
__device__ __align__(16) h16  g_qkv [ROWS*3*DD];
__device__ __align__(16) h16  g_o   [ROWS*DD];
__device__ __align__(16) float g_x1 [ROWS*DD];
__device__ __align__(16) h16  g_h2  [ROWS*DD];
__device__ __align__(16) h16  g_ff1 [ROWS*FF];
__device__ __align__(16) h16  g_qkvw[3*DD*DD];
__device__ __align__(16) h16  g_outw[DD*DD];
__device__ __align__(16) h16  g_fc1w[FF*DD];
__device__ __align__(16) h16  g_fc2w[DD*FF];

// -------------------- helpers --------------------
__device__ __forceinline__ uint32_t smem_u32(const void* p){
    uint32_t a;
    asm("{ .reg .u64 t; cvta.to.shared.u64 t, %1; cvt.u32.u64 %0, t; }"
        : "=r"(a) : "l"(p));
    return a;
}
__device__ __forceinline__ void ldsm_x4(uint32_t* r, uint32_t a){
    asm volatile("ldmatrix.sync.aligned.m8n8.x4.shared.b16 {%0,%1,%2,%3}, [%4];"
        : "=r"(r[0]),"=r"(r[1]),"=r"(r[2]),"=r"(r[3]) : "r"(a));
}
__device__ __forceinline__ void ldsm_x4t(uint32_t* r, uint32_t a){
    asm volatile("ldmatrix.sync.aligned.m8n8.x4.trans.shared.b16 {%0,%1,%2,%3}, [%4];"
        : "=r"(r[0]),"=r"(r[1]),"=r"(r[2]),"=r"(r[3]) : "r"(a));
}
__device__ __forceinline__ void mma16816(float* c, const uint32_t* a, const uint32_t* b){
    asm volatile(
        "mma.sync.aligned.m16n8k16.row.col.f32.f16.f16.f32 "
        "{%0,%1,%2,%3}, {%4,%5,%6,%7}, {%8,%9}, {%0,%1,%2,%3};"
        : "+f"(c[0]),"+f"(c[1]),"+f"(c[2]),"+f"(c[3])
        : "r"(a[0]),"r"(a[1]),"r"(a[2]),"r"(a[3]), "r"(b[0]),"r"(b[1]));
}
#define CP_ASYNC16(dst, src) \
    asm volatile("cp.async.cg.shared.global [%0], [%1], 16;" :: "r"(dst), "l"(src))
#define CP_COMMIT() asm volatile("cp.async.commit_group;" ::: "memory")
#define CP_WAIT0()  asm volatile("cp.async.wait_group 0;" ::: "memory")

static __device__ __forceinline__ uint32_t packf2(float a, float b){
    __half2 h = __floats2half2_rn(a, b);
    return *reinterpret_cast<uint32_t*>(&h);
}
static __device__ __forceinline__ __half2 u2h2(uint32_t u){
    return *reinterpret_cast<__half2*>(&u);
}
static __device__ __forceinline__ uint32_t h2u2(__half2 h){
    return *reinterpret_cast<uint32_t*>(&h);
}

#define SCLQ 0.18033688011112042f   // 0.125 * log2(e), folded into Q at QKV epilogue

// -------------------- fused weight convert + ln1 (one launch) --------------------
__global__ __launch_bounds__(256) void prep_all(
    const float* __restrict__ w0, h16* __restrict__ o0,
    const float* __restrict__ w1, h16* __restrict__ o1,
    const float* __restrict__ w2, h16* __restrict__ o2,
    const float* __restrict__ w3, h16* __restrict__ o3,
    const float* __restrict__ x,  const float* __restrict__ lw,
    const float* __restrict__ lb, h16* __restrict__ y)
{
    __shared__ float red[256];
    int tid = threadIdx.x;
    if (blockIdx.x < 6912) {
        int i = blockIdx.x * 256 + tid;
        const float* w; h16* o; int j;
        if (i < 442368)       { w = w0; o = o0; j = i; }
        else if (i < 589824)  { w = w1; o = o1; j = i - 442368; }
        else if (i < 1179648) { w = w2; o = o2; j = i - 589824; }
        else                  { w = w3; o = o3; j = i - 1179648; }
        float4 v = reinterpret_cast<const float4*>(w)[j];
        uint2 r;
        r.x = packf2(v.x, v.y);
        r.y = packf2(v.z, v.w);
        reinterpret_cast<uint2*>(o)[j] = r;
        return;
    }
    int row = blockIdx.x - 6912;
    const float* xr = x + (size_t)row * DD;
    h16* yr = y + (size_t)row * DD;
    float v0 = xr[tid], v1 = xr[tid + 256], v2 = xr[tid + 512];
    red[tid] = v0 + v1 + v2;
    __syncthreads();
    for (int off = 128; off; off >>= 1) {
        if (tid < off) red[tid] += red[tid + off];
        __syncthreads();
    }
    float mean = red[0] * (1.0f / DD);
    __syncthreads();
    float d0 = v0 - mean, d1 = v1 - mean, d2 = v2 - mean;
    red[tid] = d0*d0 + d1*d1 + d2*d2;
    __syncthreads();
    for (int off = 128; off; off >>= 1) {
        if (tid < off) red[tid] += red[tid + off];
        __syncthreads();
    }
    float rstd = rsqrtf(red[0] * (1.0f / DD) + 1e-5f);
    yr[tid]       = __float2half_rn(d0 * rstd * lw[tid]       + lb[tid]);
    yr[tid + 256] = __float2half_rn(d1 * rstd * lw[tid + 256] + lb[tid + 256]);
    yr[tid + 512] = __float2half_rn(d2 * rstd * lw[tid + 512] + lb[tid + 512]);
}

// -------------------- layernorm -> fp16 (ln2) --------------------
__global__ __launch_bounds__(256) void ln_h(const float* __restrict__ x,
                                            const float* __restrict__ w,
                                            const float* __restrict__ b,
                                            h16* __restrict__ y)
{
    __shared__ float red[256];
    int tid = threadIdx.x;
    const float* xr = x + (size_t)blockIdx.x * DD;
    h16* yr = y + (size_t)blockIdx.x * DD;
    float v0 = xr[tid], v1 = xr[tid + 256], v2 = xr[tid + 512];
    red[tid] = v0 + v1 + v2;
    __syncthreads();
    for (int off = 128; off; off >>= 1) {
        if (tid < off) red[tid] += red[tid + off];
        __syncthreads();
    }
    float mean = red[0] * (1.0f / DD);
    __syncthreads();
    float d0 = v0 - mean, d1 = v1 - mean, d2 = v2 - mean;
    red[tid] = d0*d0 + d1*d1 + d2*d2;
    __syncthreads();
    for (int off = 128; off; off >>= 1) {
        if (tid < off) red[tid] += red[tid + off];
        __syncthreads();
    }
    float rstd = rsqrtf(red[0] * (1.0f / DD) + 1e-5f);
    yr[tid]       = __float2half_rn(d0 * rstd * w[tid]       + b[tid]);
    yr[tid + 256] = __float2half_rn(d1 * rstd * w[tid + 256] + b[tid + 256]);
    yr[tid + 512] = __float2half_rn(d2 * rstd * w[tid + 512] + b[tid + 512]);
}

// -------------------- flash attention (fp16, causal, K+V dbl-buffered) ----------
__global__ __launch_bounds__(256) void flash_attn(
    const h16* __restrict__ qkv,
    h16* __restrict__ os)
{
    constexpr int STR = 144;
    constexpr int PL  = 128 * STR;       // 18432 per plane
    extern __shared__ __align__(128) char smem[];

    const int qt = gridDim.x - 1 - blockIdx.x;   // longest jobs first
    const int bh = blockIdx.y;
    const int b = bh / HH, h = bh % HH;
    const int tid = threadIdx.x, wid = tid >> 5, lane = tid & 31;
    const uint32_t sb = smem_u32(smem);

    const h16* Qb = qkv + (size_t)(b * SS + qt * 128) * (3 * DD) + h * HDD;
    const h16* Kb = qkv + (size_t)(b * SS) * (3 * DD) + DD + h * HDD;
    const h16* Vb = Kb + DD;

    auto loadQ = [&]() {
#pragma unroll
        for (int it = 0; it < 4; it++) {
            int idx = tid + it * 256;
            int r = idx >> 3, c = idx & 7;
            CP_ASYNC16(sb + r * STR + c * 16,
                       Qb + (size_t)r * (3 * DD) + c * 8);
        }
        CP_COMMIT();
    };
    auto loadKV = [&](int j, int vb) {
#pragma unroll
        for (int it = 0; it < 4; it++) {
            int idx = tid + it * 256;
            int r = idx >> 3, c = idx & 7;
            CP_ASYNC16(sb + (1 + vb) * PL + r * STR + c * 16,
                       Kb + (size_t)(j * 128 + r) * (3 * DD) + c * 8);
        }
#pragma unroll
        for (int it = 0; it < 4; it++) {
            int idx = tid + it * 256;
            int r = idx >> 3, c = idx & 7;
            CP_ASYNC16(sb + (3 + vb) * PL + r * STR + c * 16,
                       Vb + (size_t)(j * 128 + r) * (3 * DD) + c * 8);
        }
        CP_COMMIT();
    };

    loadQ();
    loadKV(0, 0);

    float mo0 = -1e30f, mo1 = -1e30f;
    float l0 = 0.f, l1 = 0.f;
    float oacc[8][4];
#pragma unroll
    for (int f = 0; f < 8; f++)
#pragma unroll
        for (int c = 0; c < 4; c++) oacc[f][c] = 0.f;

    for (int j = 0; j <= qt; j++) {
        const int vb = j & 1;
        CP_WAIT0();
        __syncthreads();

        // ---- S = Q K^T ----
        float sacc[16][4];
#pragma unroll
        for (int f = 0; f < 16; f++)
#pragma unroll
            for (int c = 0; c < 4; c++) sacc[f][c] = 0.f;

#pragma unroll
        for (int ks = 0; ks < 4; ks++) {
            uint32_t aQ[4];
            uint32_t qaddr = sb + (wid * 16 + (lane & 15)) * STR + ks * 32 + ((lane >> 4) << 4);
            ldsm_x4(aQ, qaddr);
#pragma unroll
            for (int h8 = 0; h8 < 8; h8++) {
                uint32_t row = h8 * 16 + (lane & 7) + ((lane >> 4) << 3);
                uint32_t ch  = (lane >> 3) & 1;
                uint32_t ka  = sb + (1 + vb) * PL + row * STR + ks * 32 + ch * 16;
                uint32_t bK[4];
                ldsm_x4(bK, ka);
                mma16816(sacc[2*h8],   aQ, bK);
                mma16816(sacc[2*h8+1], aQ, bK + 2);
            }
        }

        // ---- online softmax (log2 domain) ----
        const bool diag = (j == qt);
        int rl0 = wid * 16 + (lane >> 2), rl1 = rl0 + 8;
        float mn0 = mo0, mn1 = mo1;
#pragma unroll
        for (int f = 0; f < 16; f++) {
            int cl = f * 8 + (lane & 3) * 2;
            float t0 = sacc[f][0], t1 = sacc[f][1];
            float t2 = sacc[f][2], t3 = sacc[f][3];
            if (diag) {
                if (cl     > rl0) t0 = -1e30f;
                if (cl + 1 > rl0) t1 = -1e30f;
                if (cl     > rl1) t2 = -1e30f;
                if (cl + 1 > rl1) t3 = -1e30f;
            }
            sacc[f][0] = t0; sacc[f][1] = t1; sacc[f][2] = t2; sacc[f][3] = t3;
            mn0 = fmaxf(mn0, fmaxf(t0, t1));
            mn1 = fmaxf(mn1, fmaxf(t2, t3));
        }
        mn0 = fmaxf(mn0, __shfl_xor_sync(0xffffffffu, mn0, 1));
        mn0 = fmaxf(mn0, __shfl_xor_sync(0xffffffffu, mn0, 2));
        mn1 = fmaxf(mn1, __shfl_xor_sync(0xffffffffu, mn1, 1));
        mn1 = fmaxf(mn1, __shfl_xor_sync(0xffffffffu, mn1, 2));

        float f0 = exp2f(mo0 - mn0), f1 = exp2f(mo1 - mn1);
        l0 *= f0; l1 *= f1;
#pragma unroll
        for (int f = 0; f < 8; f++) {
            oacc[f][0] *= f0; oacc[f][1] *= f0;
            oacc[f][2] *= f1; oacc[f][3] *= f1;
        }
        uint32_t pr0[16], pr1[16];
#pragma unroll
        for (int f = 0; f < 16; f++) {
            __half2 ha = __floats2half2_rn(sacc[f][0] - mn0, sacc[f][1] - mn0);
            __half2 hb = __floats2half2_rn(sacc[f][2] - mn1, sacc[f][3] - mn1);
            pr0[f] = h2u2(h2exp2(ha));
            pr1[f] = h2u2(h2exp2(hb));
        }
        float s0 = 0.f, s1 = 0.f;
#pragma unroll
        for (int i = 0; i < 8; i++) {
            __half2 qa = __hadd2(u2h2(pr0[2*i]), u2h2(pr0[2*i+1]));
            __half2 qb = __hadd2(u2h2(pr1[2*i]), u2h2(pr1[2*i+1]));
            s0 += __low2float(qa) + __high2float(qa);
            s1 += __low2float(qb) + __high2float(qb);
        }
        s0 += __shfl_xor_sync(0xffffffffu, s0, 1);
        s0 += __shfl_xor_sync(0xffffffffu, s0, 2);
        s1 += __shfl_xor_sync(0xffffffffu, s1, 1);
        s1 += __shfl_xor_sync(0xffffffffu, s1, 2);
        l0 += s0; l1 += s1;
        mo0 = mn0; mo1 = mn1;

        if (j < qt) loadKV(j + 1, vb ^ 1);

        // ---- O += P V_j ----
#pragma unroll
        for (int kk = 0; kk < 8; kk++) {
            uint32_t aP[4] = { pr0[2*kk], pr1[2*kk], pr0[2*kk+1], pr1[2*kk+1] };
#pragma unroll
            for (int h4 = 0; h4 < 4; h4++) {
                uint32_t row = kk * 16 + (lane & 7) + (((lane >> 3) & 1) << 3);
                uint32_t col = h4 * 16 + ((lane >> 4) << 3);
                uint32_t va  = sb + (3 + vb) * PL + row * STR + col * 2;
                uint32_t bV[4];
                ldsm_x4t(bV, va);
                mma16816(oacc[2*h4],   aP, bV);
                mma16816(oacc[2*h4+1], aP, bV + 2);
            }
        }
    }

    float li0 = 1.0f / l0, li1 = 1.0f / l1;
    int m0r = b * SS + qt * 128 + wid * 16 + (lane >> 2);
    h16* oh = os + (size_t)m0r * DD + h * HDD;
#pragma unroll
    for (int f = 0; f < 8; f++) {
        int n = f * 8 + (lane & 3) * 2;
        *reinterpret_cast<uint32_t*>(oh + n) =
            packf2(oacc[f][0] * li0, oacc[f][1] * li0);
        *reinterpret_cast<uint32_t*>(oh + 8 * DD + n) =
            packf2(oacc[f][2] * li1, oacc[f][3] * li1);
    }
}

// -------------------- fp16 warp-MMA GEMM, BK=64, cp.async dbl-buffered --------
// One __syncthreads per k-tile (trailing sync removed; top sync of iter kt+1
// guarantees all warps finished compute kt before load(kt+2) reuses its buffer).
enum { EPI_QKV = 0, EPI_BIASRES = 1, EPI_GELU = 2 };

template<int BN, int EPI, bool OUT_HALF>
__global__ __launch_bounds__(256, 2) void mma_gemm2(
    const h16* __restrict__ A, const h16* __restrict__ Bm,
    const float* __restrict__ bias, const float* __restrict__ resid,
    void* __restrict__ Cout,
    int K, int lda, int ldb, int ldc)
{
    constexpr int BM = 128, BK = 64;
    constexpr int ASTR = 144;
    constexpr int APL  = BM * ASTR;      // 18432
    constexpr int BSTR = 144;
    constexpr int BPL  = BN * BSTR;      // 18432 / 9216
    constexpr int BUF  = APL + BPL;
    constexpr int MF = (BN == 128) ? 4 : 2;
    constexpr int NF = 4;

    extern __shared__ __align__(128) char smem[];

    const int m0 = blockIdx.y * BM, n0 = blockIdx.x * BN;
    const int tid = threadIdx.x, wid = tid >> 5, lane = tid & 31;
    const int wm0 = (BN == 128) ? (wid & 1) * 64 : (wid & 3) * 32;
    const int wn0 = (BN == 128) ? (wid >> 1) * 32 : (wid >> 2) * 32;
    const uint32_t sb = smem_u32(smem);

    float acc[MF][NF][4];
#pragma unroll
    for (int i = 0; i < MF; i++)
#pragma unroll
        for (int jj = 0; jj < NF; jj++)
#pragma unroll
            for (int c = 0; c < 4; c++) acc[i][jj][c] = 0.f;

    int NT = K / BK;

    auto load_tile = [&](int kt, int bsel) {
        uint32_t base = sb + bsel * BUF;
#pragma unroll
        for (int it = 0; it < 4; it++) {
            int idx = tid + it * 256;
            int r = idx >> 3, c = idx & 7;
            const h16* src = A + (size_t)(m0 + r) * lda + kt * BK + c * 8;
            CP_ASYNC16(base + r * ASTR + c * 16, src);
        }
#pragma unroll
        for (int it = 0; it < BN / 32; it++) {
            int idx = tid + it * 256;
            int r = idx >> 3, c = idx & 7;
            const h16* src = Bm + (size_t)(n0 + r) * ldb + kt * BK + c * 8;
            CP_ASYNC16(base + APL + r * BSTR + c * 16, src);
        }
        CP_COMMIT();
    };

    load_tile(0, 0);

    for (int kt = 0; kt < NT; kt++) {
        int buf = kt & 1;
        CP_WAIT0();
        __syncthreads();
        if (kt + 1 < NT) load_tile(kt + 1, buf ^ 1);

        uint32_t base = sb + buf * BUF;
#pragma unroll
        for (int ks = 0; ks < 4; ks++) {
            uint32_t bB[NF][2];
#pragma unroll
            for (int hh = 0; hh < 2; hh++) {
                uint32_t row = wn0 + hh * 16 + (lane & 7) + ((lane >> 4) << 3);
                uint32_t ch  = (lane >> 3) & 1;
                uint32_t ad  = base + APL + row * BSTR + ks * 32 + ch * 16;
                uint32_t r4[4];
                ldsm_x4(r4, ad);
                bB[hh*2][0]=r4[0]; bB[hh*2][1]=r4[1]; bB[hh*2+1][0]=r4[2]; bB[hh*2+1][1]=r4[3];
            }
#pragma unroll
            for (int mf = 0; mf < MF; mf++) {
                uint32_t row = wm0 + mf * 16 + (lane & 15);
                uint32_t ch  = lane >> 4;
                uint32_t ad  = base + row * ASTR + ks * 32 + ch * 16;
                uint32_t aA[4];
                ldsm_x4(aA, ad);
#pragma unroll
                for (int nf = 0; nf < NF; nf++)
                    mma16816(acc[mf][nf], aA, bB[nf]);
            }
        }
        // no trailing sync — next iteration's top sync covers buffer reuse
    }

    // -------- epilogue --------
#pragma unroll
    for (int mf = 0; mf < MF; mf++) {
#pragma unroll
        for (int half = 0; half < 2; half++) {
            int m = m0 + wm0 + mf * 16 + (lane >> 2) + half * 8;
#pragma unroll
            for (int nf = 0; nf < NF; nf++) {
                int n = n0 + wn0 + nf * 8 + (lane & 3) * 2;
                float v0 = acc[mf][nf][half*2 + 0];
                float v1 = acc[mf][nf][half*2 + 1];
                if (bias) { v0 += __ldg(&bias[n]); v1 += __ldg(&bias[n+1]); }
                if (EPI == EPI_QKV) {
                    if (n < DD)     v0 *= SCLQ;
                    if (n + 1 < DD) v1 *= SCLQ;
                }
                if (EPI == EPI_GELU) {
                    v0 = 0.5f * v0 * (1.0f + erff(v0 * 0.70710678118654752f));
                    v1 = 0.5f * v1 * (1.0f + erff(v1 * 0.70710678118654752f));
                }
                if (EPI == EPI_BIASRES) {
                    const float* Rrow = resid + (size_t)m * ldc;
                    v0 += Rrow[n]; v1 += Rrow[n+1];
                }
                if (OUT_HALF) {
                    h16* Ch = (h16*)Cout + (size_t)m * ldc;
                    *reinterpret_cast<uint32_t*>(Ch + n) = packf2(v0, v1);
                } else {
                    float* Crow = (float*)Cout + (size_t)m * ldc;
                    *reinterpret_cast<float2*>(Crow + n) = make_float2(v0, v1);
                }
            }
        }
    }
}

// -------------------- host launcher --------------------
extern "C" void kernel_launch(void* const* d_in, const int* in_sizes, int n_in,
                              void* d_out, int out_size)
{
    const float* x     = (const float*)d_in[0];
    const float* qkv_w = (const float*)d_in[2];
    const float* qkv_b = (const float*)d_in[3];
    const float* out_w = (const float*)d_in[4];
    const float* out_b = (const float*)d_in[5];
    const float* fc1_w = (const float*)d_in[6];
    const float* fc1_b = (const float*)d_in[7];
    const float* fc2_w = (const float*)d_in[8];
    const float* fc2_b = (const float*)d_in[9];
    const float* ln1_w = (const float*)d_in[10];
    const float* ln1_b = (const float*)d_in[11];
    const float* ln2_w = (const float*)d_in[12];
    const float* ln2_b = (const float*)d_in[13];
    float* out = (float*)d_out;

    void *p0,*p1,*p4,*p5,*p6,*p7,*p8,*p9,*p10,*p11;
    cudaGetSymbolAddress(&p0,  g_hx);
    cudaGetSymbolAddress(&p1,  g_qkv);
    cudaGetSymbolAddress(&p4,  g_o);
    cudaGetSymbolAddress(&p5,  g_x1);
    cudaGetSymbolAddress(&p6,  g_h2);
    cudaGetSymbolAddress(&p7,  g_ff1);
    cudaGetSymbolAddress(&p8,  g_qkvw);
    cudaGetSymbolAddress(&p9,  g_outw);
    cudaGetSymbolAddress(&p10, g_fc1w);
    cudaGetSymbolAddress(&p11, g_fc2w);
    h16* hx   = (h16*)p0;  h16* qkv  = (h16*)p1;
    h16* o    = (h16*)p4;  float* x1 = (float*)p5;
    h16* h2   = (h16*)p6;  h16* ff1  = (h16*)p7;
    h16* qkvw = (h16*)p8;  h16* outw = (h16*)p9;
    h16* fc1w = (h16*)p10; h16* fc2w = (h16*)p11;

    const int SMEM_G128 = 2 * (18432 + 18432);   // 73728
    const int SMEM_G64  = 2 * (18432 + 9216);    // 55296
    const int SMEM_FA   = 5 * 128 * 144;         // 92160

    cudaFuncSetAttribute(mma_gemm2<128,EPI_QKV,    true >,
                         cudaFuncAttributeMaxDynamicSharedMemorySize, SMEM_G128);
    cudaFuncSetAttribute(mma_gemm2<64, EPI_BIASRES,false>,
                         cudaFuncAttributeMaxDynamicSharedMemorySize, SMEM_G64);
    cudaFuncSetAttribute(mma_gemm2<64, EPI_GELU,   true >,
                         cudaFuncAttributeMaxDynamicSharedMemorySize, SMEM_G64);
    cudaFuncSetAttribute(flash_attn,
                         cudaFuncAttributeMaxDynamicSharedMemorySize, SMEM_FA);

    // 0+1. weight converts + ln1 fused
    prep_all<<<6912 + ROWS, 256>>>(qkv_w, qkvw, out_w, outw,
                                   fc1_w, fc1w, fc2_w, fc2w,
                                   x, ln1_w, ln1_b, hx);

    // 2. QKV (Q pre-scaled in epilogue)
    mma_gemm2<128,EPI_QKV,true>
        <<<dim3(3*DD/128, ROWS/128, 1), 256, SMEM_G128>>>(
            hx, qkvw, qkv_b, nullptr, qkv,
            DD, DD, DD, 3*DD);

    // 3-5. flash attention -> o fp16
    flash_attn<<<dim3(SS/128, BH), 256, SMEM_FA>>>(qkv, o);

    // 6. x1 = x + O @ out_w^T + out_b   (fp32 out; BN=64)
    mma_gemm2<64,EPI_BIASRES,false>
        <<<dim3(DD/64, ROWS/128, 1), 256, SMEM_G64>>>(
            o, outw, out_b, x, x1,
            DD, DD, DD, DD);

    // 7. ln2 -> h2 fp16
    ln_h<<<ROWS, 256>>>(x1, ln2_w, ln2_b, h2);

    // 8. ff1 = gelu(h2 @ fc1_w^T + fc1_b) -> fp16  (BN=64: 1536 CTAs, smooth waves)
    mma_gemm2<64,EPI_GELU,true>
        <<<dim3(FF/64, ROWS/128, 1), 256, SMEM_G64>>>(
            h2, fc1w, fc1_b, nullptr, ff1,
            DD, DD, DD, FF);

    // 9. out = x1 + ff1 @ fc2_w^T + fc2_b   (fp32 out; BN=64)
    mma_gemm2<64,EPI_BIASRES,false>
        <<<dim3(DD/64, ROWS/128, 1), 256, SMEM_G64>>>(
            ff1, fc2w, fc2_b, x1, out,
            FF, FF, FF, DD);
}

// round 16
// speedup vs baseline: 1.0277x; 1.0277x over previous
#include <cuda_runtime.h>
#include <cuda_fp16.h>
#include <math.h>
#include <stdint.h>

typedef __half h16;

// Problem constants
#define BB 2
#define SS 2048
#define DD 768
#define HH 12
#define FF 3072
#define HDD 64
#define ROWS (BB*SS)          // 4096
#define BH (BB*HH)            // 24

// -------------------- device scratch (single fp16 activations) --------------------
__device__ __align__(16) h16  g_hx  [ROWS*DD];
__device__ __align__(16) h16  g_qkv [ROWS*3*DD];
__device__ __align__(16) h16  g_o   [ROWS*DD];
__device__ __align__(16) float g_x1 [ROWS*DD];
__device__ __align__(16) h16  g_h2  [ROWS*DD];
__device__ __align__(16) h16  g_ff1 [ROWS*FF];
__device__ __align__(16) h16  g_qkvw[3*DD*DD];
__device__ __align__(16) h16  g_outw[DD*DD];
__device__ __align__(16) h16  g_fc1w[FF*DD];
__device__ __align__(16) h16  g_fc2w[DD*FF];

// -------------------- helpers --------------------
__device__ __forceinline__ uint32_t smem_u32(const void* p){
    uint32_t a;
    asm("{ .reg .u64 t; cvta.to.shared.u64 t, %1; cvt.u32.u64 %0, t; }"
        : "=r"(a) : "l"(p));
    return a;
}
__device__ __forceinline__ void ldsm_x4(uint32_t* r, uint32_t a){
    asm volatile("ldmatrix.sync.aligned.m8n8.x4.shared.b16 {%0,%1,%2,%3}, [%4];"
        : "=r"(r[0]),"=r"(r[1]),"=r"(r[2]),"=r"(r[3]) : "r"(a));
}
__device__ __forceinline__ void ldsm_x4t(uint32_t* r, uint32_t a){
    asm volatile("ldmatrix.sync.aligned.m8n8.x4.trans.shared.b16 {%0,%1,%2,%3}, [%4];"
        : "=r"(r[0]),"=r"(r[1]),"=r"(r[2]),"=r"(r[3]) : "r"(a));
}
__device__ __forceinline__ void mma16816(float* c, const uint32_t* a, const uint32_t* b){
    asm volatile(
        "mma.sync.aligned.m16n8k16.row.col.f32.f16.f16.f32 "
        "{%0,%1,%2,%3}, {%4,%5,%6,%7}, {%8,%9}, {%0,%1,%2,%3};"
        : "+f"(c[0]),"+f"(c[1]),"+f"(c[2]),"+f"(c[3])
        : "r"(a[0]),"r"(a[1]),"r"(a[2]),"r"(a[3]), "r"(b[0]),"r"(b[1]));
}
#define CP_ASYNC16(dst, src) \
    asm volatile("cp.async.cg.shared.global [%0], [%1], 16;" :: "r"(dst), "l"(src))
#define CP_COMMIT() asm volatile("cp.async.commit_group;" ::: "memory")
#define CP_WAIT0()  asm volatile("cp.async.wait_group 0;" ::: "memory")
#define CP_WAIT1()  asm volatile("cp.async.wait_group 1;" ::: "memory")

static __device__ __forceinline__ uint32_t packf2(float a, float b){
    __half2 h = __floats2half2_rn(a, b);
    return *reinterpret_cast<uint32_t*>(&h);
}
static __device__ __forceinline__ __half2 u2h2(uint32_t u){
    return *reinterpret_cast<__half2*>(&u);
}
static __device__ __forceinline__ uint32_t h2u2(__half2 h){
    return *reinterpret_cast<uint32_t*>(&h);
}

#define SCLQ 0.18033688011112042f   // 0.125 * log2(e), folded into Q at QKV epilogue

// -------------------- fused weight convert + ln1 (one launch) --------------------
__global__ __launch_bounds__(256) void prep_all(
    const float* __restrict__ w0, h16* __restrict__ o0,
    const float* __restrict__ w1, h16* __restrict__ o1,
    const float* __restrict__ w2, h16* __restrict__ o2,
    const float* __restrict__ w3, h16* __restrict__ o3,
    const float* __restrict__ x,  const float* __restrict__ lw,
    const float* __restrict__ lb, h16* __restrict__ y)
{
    __shared__ float red[256];
    int tid = threadIdx.x;
    if (blockIdx.x < 6912) {
        int i = blockIdx.x * 256 + tid;
        const float* w; h16* o; int j;
        if (i < 442368)       { w = w0; o = o0; j = i; }
        else if (i < 589824)  { w = w1; o = o1; j = i - 442368; }
        else if (i < 1179648) { w = w2; o = o2; j = i - 589824; }
        else                  { w = w3; o = o3; j = i - 1179648; }
        float4 v = reinterpret_cast<const float4*>(w)[j];
        uint2 r;
        r.x = packf2(v.x, v.y);
        r.y = packf2(v.z, v.w);
        reinterpret_cast<uint2*>(o)[j] = r;
        return;
    }
    int row = blockIdx.x - 6912;
    const float* xr = x + (size_t)row * DD;
    h16* yr = y + (size_t)row * DD;
    float v0 = xr[tid], v1 = xr[tid + 256], v2 = xr[tid + 512];
    red[tid] = v0 + v1 + v2;
    __syncthreads();
    for (int off = 128; off; off >>= 1) {
        if (tid < off) red[tid] += red[tid + off];
        __syncthreads();
    }
    float mean = red[0] * (1.0f / DD);
    __syncthreads();
    float d0 = v0 - mean, d1 = v1 - mean, d2 = v2 - mean;
    red[tid] = d0*d0 + d1*d1 + d2*d2;
    __syncthreads();
    for (int off = 128; off; off >>= 1) {
        if (tid < off) red[tid] += red[tid + off];
        __syncthreads();
    }
    float rstd = rsqrtf(red[0] * (1.0f / DD) + 1e-5f);
    yr[tid]       = __float2half_rn(d0 * rstd * lw[tid]       + lb[tid]);
    yr[tid + 256] = __float2half_rn(d1 * rstd * lw[tid + 256] + lb[tid + 256]);
    yr[tid + 512] = __float2half_rn(d2 * rstd * lw[tid + 512] + lb[tid + 512]);
}

// -------------------- layernorm -> fp16 (ln2) --------------------
__global__ __launch_bounds__(256) void ln_h(const float* __restrict__ x,
                                            const float* __restrict__ w,
                                            const float* __restrict__ b,
                                            h16* __restrict__ y)
{
    __shared__ float red[256];
    int tid = threadIdx.x;
    const float* xr = x + (size_t)blockIdx.x * DD;
    h16* yr = y + (size_t)blockIdx.x * DD;
    float v0 = xr[tid], v1 = xr[tid + 256], v2 = xr[tid + 512];
    red[tid] = v0 + v1 + v2;
    __syncthreads();
    for (int off = 128; off; off >>= 1) {
        if (tid < off) red[tid] += red[tid + off];
        __syncthreads();
    }
    float mean = red[0] * (1.0f / DD);
    __syncthreads();
    float d0 = v0 - mean, d1 = v1 - mean, d2 = v2 - mean;
    red[tid] = d0*d0 + d1*d1 + d2*d2;
    __syncthreads();
    for (int off = 128; off; off >>= 1) {
        if (tid < off) red[tid] += red[tid + off];
        __syncthreads();
    }
    float rstd = rsqrtf(red[0] * (1.0f / DD) + 1e-5f);
    yr[tid]       = __float2half_rn(d0 * rstd * w[tid]       + b[tid]);
    yr[tid + 256] = __float2half_rn(d1 * rstd * w[tid + 256] + b[tid + 256]);
    yr[tid + 512] = __float2half_rn(d2 * rstd * w[tid + 512] + b[tid + 512]);
}

// -------------------- flash attention (fp16, causal, K+V dbl-buffered) ----------
__global__ __launch_bounds__(256) void flash_attn(
    const h16* __restrict__ qkv,
    h16* __restrict__ os)
{
    constexpr int STR = 144;
    constexpr int PL  = 128 * STR;       // 18432 per plane
    extern __shared__ __align__(128) char smem[];

    const int qt = gridDim.x - 1 - blockIdx.x;   // longest jobs first
    const int bh = blockIdx.y;
    const int b = bh / HH, h = bh % HH;
    const int tid = threadIdx.x, wid = tid >> 5, lane = tid & 31;
    const uint32_t sb = smem_u32(smem);

    const h16* Qb = qkv + (size_t)(b * SS + qt * 128) * (3 * DD) + h * HDD;
    const h16* Kb = qkv + (size_t)(b * SS) * (3 * DD) + DD + h * HDD;
    const h16* Vb = Kb + DD;

    auto loadQ = [&]() {
#pragma unroll
        for (int it = 0; it < 4; it++) {
            int idx = tid + it * 256;
            int r = idx >> 3, c = idx & 7;
            CP_ASYNC16(sb + r * STR + c * 16,
                       Qb + (size_t)r * (3 * DD) + c * 8);
        }
        CP_COMMIT();
    };
    auto loadKV = [&](int j, int vb) {
#pragma unroll
        for (int it = 0; it < 4; it++) {
            int idx = tid + it * 256;
            int r = idx >> 3, c = idx & 7;
            CP_ASYNC16(sb + (1 + vb) * PL + r * STR + c * 16,
                       Kb + (size_t)(j * 128 + r) * (3 * DD) + c * 8);
        }
#pragma unroll
        for (int it = 0; it < 4; it++) {
            int idx = tid + it * 256;
            int r = idx >> 3, c = idx & 7;
            CP_ASYNC16(sb + (3 + vb) * PL + r * STR + c * 16,
                       Vb + (size_t)(j * 128 + r) * (3 * DD) + c * 8);
        }
        CP_COMMIT();
    };

    loadQ();
    loadKV(0, 0);

    float mo0 = -1e30f, mo1 = -1e30f;
    float l0 = 0.f, l1 = 0.f;
    float oacc[8][4];
#pragma unroll
    for (int f = 0; f < 8; f++)
#pragma unroll
        for (int c = 0; c < 4; c++) oacc[f][c] = 0.f;

    for (int j = 0; j <= qt; j++) {
        const int vb = j & 1;
        CP_WAIT0();
        __syncthreads();

        // ---- S = Q K^T ----
        float sacc[16][4];
#pragma unroll
        for (int f = 0; f < 16; f++)
#pragma unroll
            for (int c = 0; c < 4; c++) sacc[f][c] = 0.f;

#pragma unroll
        for (int ks = 0; ks < 4; ks++) {
            uint32_t aQ[4];
            uint32_t qaddr = sb + (wid * 16 + (lane & 15)) * STR + ks * 32 + ((lane >> 4) << 4);
            ldsm_x4(aQ, qaddr);
#pragma unroll
            for (int h8 = 0; h8 < 8; h8++) {
                uint32_t row = h8 * 16 + (lane & 7) + ((lane >> 4) << 3);
                uint32_t ch  = (lane >> 3) & 1;
                uint32_t ka  = sb + (1 + vb) * PL + row * STR + ks * 32 + ch * 16;
                uint32_t bK[4];
                ldsm_x4(bK, ka);
                mma16816(sacc[2*h8],   aQ, bK);
                mma16816(sacc[2*h8+1], aQ, bK + 2);
            }
        }

        // ---- online softmax (log2 domain) ----
        const bool diag = (j == qt);
        int rl0 = wid * 16 + (lane >> 2), rl1 = rl0 + 8;
        float mn0 = mo0, mn1 = mo1;
#pragma unroll
        for (int f = 0; f < 16; f++) {
            int cl = f * 8 + (lane & 3) * 2;
            float t0 = sacc[f][0], t1 = sacc[f][1];
            float t2 = sacc[f][2], t3 = sacc[f][3];
            if (diag) {
                if (cl     > rl0) t0 = -1e30f;
                if (cl + 1 > rl0) t1 = -1e30f;
                if (cl     > rl1) t2 = -1e30f;
                if (cl + 1 > rl1) t3 = -1e30f;
            }
            sacc[f][0] = t0; sacc[f][1] = t1; sacc[f][2] = t2; sacc[f][3] = t3;
            mn0 = fmaxf(mn0, fmaxf(t0, t1));
            mn1 = fmaxf(mn1, fmaxf(t2, t3));
        }
        mn0 = fmaxf(mn0, __shfl_xor_sync(0xffffffffu, mn0, 1));
        mn0 = fmaxf(mn0, __shfl_xor_sync(0xffffffffu, mn0, 2));
        mn1 = fmaxf(mn1, __shfl_xor_sync(0xffffffffu, mn1, 1));
        mn1 = fmaxf(mn1, __shfl_xor_sync(0xffffffffu, mn1, 2));

        float f0 = exp2f(mo0 - mn0), f1 = exp2f(mo1 - mn1);
        l0 *= f0; l1 *= f1;
#pragma unroll
        for (int f = 0; f < 8; f++) {
            oacc[f][0] *= f0; oacc[f][1] *= f0;
            oacc[f][2] *= f1; oacc[f][3] *= f1;
        }
        uint32_t pr0[16], pr1[16];
#pragma unroll
        for (int f = 0; f < 16; f++) {
            __half2 ha = __floats2half2_rn(sacc[f][0] - mn0, sacc[f][1] - mn0);
            __half2 hb = __floats2half2_rn(sacc[f][2] - mn1, sacc[f][3] - mn1);
            pr0[f] = h2u2(h2exp2(ha));
            pr1[f] = h2u2(h2exp2(hb));
        }
        float s0 = 0.f, s1 = 0.f;
#pragma unroll
        for (int i = 0; i < 8; i++) {
            __half2 qa = __hadd2(u2h2(pr0[2*i]), u2h2(pr0[2*i+1]));
            __half2 qb = __hadd2(u2h2(pr1[2*i]), u2h2(pr1[2*i+1]));
            s0 += __low2float(qa) + __high2float(qa);
            s1 += __low2float(qb) + __high2float(qb);
        }
        s0 += __shfl_xor_sync(0xffffffffu, s0, 1);
        s0 += __shfl_xor_sync(0xffffffffu, s0, 2);
        s1 += __shfl_xor_sync(0xffffffffu, s1, 1);
        s1 += __shfl_xor_sync(0xffffffffu, s1, 2);
        l0 += s0; l1 += s1;
        mo0 = mn0; mo1 = mn1;

        if (j < qt) loadKV(j + 1, vb ^ 1);

        // ---- O += P V_j ----
#pragma unroll
        for (int kk = 0; kk < 8; kk++) {
            uint32_t aP[4] = { pr0[2*kk], pr1[2*kk], pr0[2*kk+1], pr1[2*kk+1] };
#pragma unroll
            for (int h4 = 0; h4 < 4; h4++) {
                uint32_t row = kk * 16 + (lane & 7) + (((lane >> 3) & 1) << 3);
                uint32_t col = h4 * 16 + ((lane >> 4) << 3);
                uint32_t va  = sb + (3 + vb) * PL + row * STR + col * 2;
                uint32_t bV[4];
                ldsm_x4t(bV, va);
                mma16816(oacc[2*h4],   aP, bV);
                mma16816(oacc[2*h4+1], aP, bV + 2);
            }
        }
    }

    float li0 = 1.0f / l0, li1 = 1.0f / l1;
    int m0r = b * SS + qt * 128 + wid * 16 + (lane >> 2);
    h16* oh = os + (size_t)m0r * DD + h * HDD;
#pragma unroll
    for (int f = 0; f < 8; f++) {
        int n = f * 8 + (lane & 3) * 2;
        *reinterpret_cast<uint32_t*>(oh + n) =
            packf2(oacc[f][0] * li0, oacc[f][1] * li0);
        *reinterpret_cast<uint32_t*>(oh + 8 * DD + n) =
            packf2(oacc[f][2] * li1, oacc[f][3] * li1);
    }
}

// -------------------- fp16 warp-MMA GEMM, BK=64, STAGES-deep cp.async --------
// One __syncthreads per k-tile. STAGES=2: classic double buffer (wait all).
// STAGES=3: preload 2 tiles; steady-state wait_group 1 gives each load ~2
// compute-tiles of latency cover. Final iteration drains (wait_group 0).
enum { EPI_QKV = 0, EPI_BIASRES = 1, EPI_GELU = 2 };

template<int BN, int STAGES, int EPI, bool OUT_HALF>
__global__ __launch_bounds__(256, 2) void mma_gemm2(
    const h16* __restrict__ A, const h16* __restrict__ Bm,
    const float* __restrict__ bias, const float* __restrict__ resid,
    void* __restrict__ Cout,
    int K, int lda, int ldb, int ldc)
{
    constexpr int BM = 128, BK = 64;
    constexpr int ASTR = 144;
    constexpr int APL  = BM * ASTR;      // 18432
    constexpr int BSTR = 144;
    constexpr int BPL  = BN * BSTR;      // 18432 / 9216
    constexpr int BUF  = APL + BPL;
    constexpr int MF = (BN == 128) ? 4 : 2;
    constexpr int NF = 4;

    extern __shared__ __align__(128) char smem[];

    const int m0 = blockIdx.y * BM, n0 = blockIdx.x * BN;
    const int tid = threadIdx.x, wid = tid >> 5, lane = tid & 31;
    const int wm0 = (BN == 128) ? (wid & 1) * 64 : (wid & 3) * 32;
    const int wn0 = (BN == 128) ? (wid >> 1) * 32 : (wid >> 2) * 32;
    const uint32_t sb = smem_u32(smem);

    float acc[MF][NF][4];
#pragma unroll
    for (int i = 0; i < MF; i++)
#pragma unroll
        for (int jj = 0; jj < NF; jj++)
#pragma unroll
            for (int c = 0; c < 4; c++) acc[i][jj][c] = 0.f;

    int NT = K / BK;

    auto load_tile = [&](int kt, int bsel) {
        uint32_t base = sb + bsel * BUF;
#pragma unroll
        for (int it = 0; it < 4; it++) {
            int idx = tid + it * 256;
            int r = idx >> 3, c = idx & 7;
            const h16* src = A + (size_t)(m0 + r) * lda + kt * BK + c * 8;
            CP_ASYNC16(base + r * ASTR + c * 16, src);
        }
#pragma unroll
        for (int it = 0; it < BN / 32; it++) {
            int idx = tid + it * 256;
            int r = idx >> 3, c = idx & 7;
            const h16* src = Bm + (size_t)(n0 + r) * ldb + kt * BK + c * 8;
            CP_ASYNC16(base + APL + r * BSTR + c * 16, src);
        }
        CP_COMMIT();
    };

    load_tile(0, 0);
    if (STAGES == 3 && NT > 1) load_tile(1, 1);

    for (int kt = 0; kt < NT; kt++) {
        int buf = kt % STAGES;
        // Guarantee tile kt resident: steady-state allows 1 in-flight group
        // (STAGES==3); final iteration must drain (R5 lesson).
        if (STAGES == 3 && kt + 1 < NT) CP_WAIT1();
        else                            CP_WAIT0();
        __syncthreads();
        int nx = kt + STAGES - 1;
        if (nx < NT) load_tile(nx, nx % STAGES);

        uint32_t base = sb + buf * BUF;
#pragma unroll
        for (int ks = 0; ks < 4; ks++) {
            uint32_t bB[NF][2];
#pragma unroll
            for (int hh = 0; hh < 2; hh++) {
                uint32_t row = wn0 + hh * 16 + (lane & 7) + ((lane >> 4) << 3);
                uint32_t ch  = (lane >> 3) & 1;
                uint32_t ad  = base + APL + row * BSTR + ks * 32 + ch * 16;
                uint32_t r4[4];
                ldsm_x4(r4, ad);
                bB[hh*2][0]=r4[0]; bB[hh*2][1]=r4[1]; bB[hh*2+1][0]=r4[2]; bB[hh*2+1][1]=r4[3];
            }
#pragma unroll
            for (int mf = 0; mf < MF; mf++) {
                uint32_t row = wm0 + mf * 16 + (lane & 15);
                uint32_t ch  = lane >> 4;
                uint32_t ad  = base + row * ASTR + ks * 32 + ch * 16;
                uint32_t aA[4];
                ldsm_x4(aA, ad);
#pragma unroll
                for (int nf = 0; nf < NF; nf++)
                    mma16816(acc[mf][nf], aA, bB[nf]);
            }
        }
        // no trailing sync — next iteration's top sync covers buffer reuse
    }

    // -------- epilogue --------
#pragma unroll
    for (int mf = 0; mf < MF; mf++) {
#pragma unroll
        for (int half = 0; half < 2; half++) {
            int m = m0 + wm0 + mf * 16 + (lane >> 2) + half * 8;
#pragma unroll
            for (int nf = 0; nf < NF; nf++) {
                int n = n0 + wn0 + nf * 8 + (lane & 3) * 2;
                float v0 = acc[mf][nf][half*2 + 0];
                float v1 = acc[mf][nf][half*2 + 1];
                if (bias) { v0 += __ldg(&bias[n]); v1 += __ldg(&bias[n+1]); }
                if (EPI == EPI_QKV) {
                    if (n < DD)     v0 *= SCLQ;
                    if (n + 1 < DD) v1 *= SCLQ;
                }
                if (EPI == EPI_GELU) {
                    v0 = 0.5f * v0 * (1.0f + erff(v0 * 0.70710678118654752f));
                    v1 = 0.5f * v1 * (1.0f + erff(v1 * 0.70710678118654752f));
                }
                if (EPI == EPI_BIASRES) {
                    const float* Rrow = resid + (size_t)m * ldc;
                    v0 += Rrow[n]; v1 += Rrow[n+1];
                }
                if (OUT_HALF) {
                    h16* Ch = (h16*)Cout + (size_t)m * ldc;
                    *reinterpret_cast<uint32_t*>(Ch + n) = packf2(v0, v1);
                } else {
                    float* Crow = (float*)Cout + (size_t)m * ldc;
                    *reinterpret_cast<float2*>(Crow + n) = make_float2(v0, v1);
                }
            }
        }
    }
}

// -------------------- host launcher --------------------
extern "C" void kernel_launch(void* const* d_in, const int* in_sizes, int n_in,
                              void* d_out, int out_size)
{
    const float* x     = (const float*)d_in[0];
    const float* qkv_w = (const float*)d_in[2];
    const float* qkv_b = (const float*)d_in[3];
    const float* out_w = (const float*)d_in[4];
    const float* out_b = (const float*)d_in[5];
    const float* fc1_w = (const float*)d_in[6];
    const float* fc1_b = (const float*)d_in[7];
    const float* fc2_w = (const float*)d_in[8];
    const float* fc2_b = (const float*)d_in[9];
    const float* ln1_w = (const float*)d_in[10];
    const float* ln1_b = (const float*)d_in[11];
    const float* ln2_w = (const float*)d_in[12];
    const float* ln2_b = (const float*)d_in[13];
    float* out = (float*)d_out;

    void *p0,*p1,*p4,*p5,*p6,*p7,*p8,*p9,*p10,*p11;
    cudaGetSymbolAddress(&p0,  g_hx);
    cudaGetSymbolAddress(&p1,  g_qkv);
    cudaGetSymbolAddress(&p4,  g_o);
    cudaGetSymbolAddress(&p5,  g_x1);
    cudaGetSymbolAddress(&p6,  g_h2);
    cudaGetSymbolAddress(&p7,  g_ff1);
    cudaGetSymbolAddress(&p8,  g_qkvw);
    cudaGetSymbolAddress(&p9,  g_outw);
    cudaGetSymbolAddress(&p10, g_fc1w);
    cudaGetSymbolAddress(&p11, g_fc2w);
    h16* hx   = (h16*)p0;  h16* qkv  = (h16*)p1;
    h16* o    = (h16*)p4;  float* x1 = (float*)p5;
    h16* h2   = (h16*)p6;  h16* ff1  = (h16*)p7;
    h16* qkvw = (h16*)p8;  h16* outw = (h16*)p9;
    h16* fc1w = (h16*)p10; h16* fc2w = (h16*)p11;

    const int SMEM_G128  = 2 * (18432 + 18432);   // 73728  (2-stage BN=128)
    const int SMEM_G64_3 = 3 * (18432 + 9216);    // 82944  (3-stage BN=64)
    const int SMEM_FA    = 5 * 128 * 144;         // 92160

    cudaFuncSetAttribute(mma_gemm2<128,2,EPI_QKV,    true >,
                         cudaFuncAttributeMaxDynamicSharedMemorySize, SMEM_G128);
    cudaFuncSetAttribute(mma_gemm2<64, 3,EPI_BIASRES,false>,
                         cudaFuncAttributeMaxDynamicSharedMemorySize, SMEM_G64_3);
    cudaFuncSetAttribute(mma_gemm2<128,2,EPI_GELU,   true >,
                         cudaFuncAttributeMaxDynamicSharedMemorySize, SMEM_G128);
    cudaFuncSetAttribute(flash_attn,
                         cudaFuncAttributeMaxDynamicSharedMemorySize, SMEM_FA);

    // 0+1. weight converts + ln1 fused
    prep_all<<<6912 + ROWS, 256>>>(qkv_w, qkvw, out_w, outw,
                                   fc1_w, fc1w, fc2_w, fc2w,
                                   x, ln1_w, ln1_b, hx);

    // 2. QKV (Q pre-scaled in epilogue) — BN=128, 2-stage
    mma_gemm2<128,2,EPI_QKV,true>
        <<<dim3(3*DD/128, ROWS/128, 1), 256, SMEM_G128>>>(
            hx, qkvw, qkv_b, nullptr, qkv,
            DD, DD, DD, 3*DD);

    // 3-5. flash attention -> o fp16
    flash_attn<<<dim3(SS/128, BH), 256, SMEM_FA>>>(qkv, o);

    // 6. x1 = x + O @ out_w^T + out_b   (fp32 out; BN=64, 3-stage)
    mma_gemm2<64,3,EPI_BIASRES,false>
        <<<dim3(DD/64, ROWS/128, 1), 256, SMEM_G64_3>>>(
            o, outw, out_b, x, x1,
            DD, DD, DD, DD);

    // 7. ln2 -> h2 fp16
    ln_h<<<ROWS, 256>>>(x1, ln2_w, ln2_b, h2);

    // 8. ff1 = gelu(h2 @ fc1_w^T + fc1_b) -> fp16  (BN=128 — R15 regression reverted)
    mma_gemm2<128,2,EPI_GELU,true>
        <<<dim3(FF/128, ROWS/128, 1), 256, SMEM_G128>>>(
            h2, fc1w, fc1_b, nullptr, ff1,
            DD, DD, DD, FF);

    // 9. out = x1 + ff1 @ fc2_w^T + fc2_b   (fp32 out; BN=64, 3-stage)
    mma_gemm2<64,3,EPI_BIASRES,false>
        <<<dim3(DD/64, ROWS/128, 1), 256, SMEM_G64_3>>>(
            ff1, fc2w, fc2_b, x1, out,
            FF, FF, FF, DD);
}

// round 17
// speedup vs baseline: 1.0285x; 1.0007x over previous
#include <cuda_runtime.h>
#include <cuda_fp16.h>
#include <math.h>
#include <stdint.h>

typedef __half h16;

// Problem constants
#define BB 2
#define SS 2048
#define DD 768
#define HH 12
#define FF 3072
#define HDD 64
#define ROWS (BB*SS)          // 4096
#define BH (BB*HH)            // 24

// -------------------- device scratch (single fp16 activations) --------------------
__device__ __align__(16) h16  g_hx  [ROWS*DD];
__device__ __align__(16) h16  g_qkv [ROWS*3*DD];
__device__ __align__(16) h16  g_o   [ROWS*DD];
__device__ __align__(16) float g_x1 [ROWS*DD];
__device__ __align__(16) h16  g_h2  [ROWS*DD];
__device__ __align__(16) h16  g_ff1 [ROWS*FF];
__device__ __align__(16) h16  g_qkvw[3*DD*DD];
__device__ __align__(16) h16  g_outw[DD*DD];
__device__ __align__(16) h16  g_fc1w[FF*DD];
__device__ __align__(16) h16  g_fc2w[DD*FF];

// -------------------- helpers --------------------
__device__ __forceinline__ uint32_t smem_u32(const void* p){
    uint32_t a;
    asm("{ .reg .u64 t; cvta.to.shared.u64 t, %1; cvt.u32.u64 %0, t; }"
        : "=r"(a) : "l"(p));
    return a;
}
__device__ __forceinline__ void ldsm_x4(uint32_t* r, uint32_t a){
    asm volatile("ldmatrix.sync.aligned.m8n8.x4.shared.b16 {%0,%1,%2,%3}, [%4];"
        : "=r"(r[0]),"=r"(r[1]),"=r"(r[2]),"=r"(r[3]) : "r"(a));
}
__device__ __forceinline__ void ldsm_x4t(uint32_t* r, uint32_t a){
    asm volatile("ldmatrix.sync.aligned.m8n8.x4.trans.shared.b16 {%0,%1,%2,%3}, [%4];"
        : "=r"(r[0]),"=r"(r[1]),"=r"(r[2]),"=r"(r[3]) : "r"(a));
}
__device__ __forceinline__ void mma16816(float* c, const uint32_t* a, const uint32_t* b){
    asm volatile(
        "mma.sync.aligned.m16n8k16.row.col.f32.f16.f16.f32 "
        "{%0,%1,%2,%3}, {%4,%5,%6,%7}, {%8,%9}, {%0,%1,%2,%3};"
        : "+f"(c[0]),"+f"(c[1]),"+f"(c[2]),"+f"(c[3])
        : "r"(a[0]),"r"(a[1]),"r"(a[2]),"r"(a[3]), "r"(b[0]),"r"(b[1]));
}
#define CP_ASYNC16(dst, src) \
    asm volatile("cp.async.cg.shared.global [%0], [%1], 16;" :: "r"(dst), "l"(src))
#define CP_COMMIT() asm volatile("cp.async.commit_group;" ::: "memory")
#define CP_WAIT0()  asm volatile("cp.async.wait_group 0;" ::: "memory")
#define CP_WAIT1()  asm volatile("cp.async.wait_group 1;" ::: "memory")

static __device__ __forceinline__ uint32_t packf2(float a, float b){
    __half2 h = __floats2half2_rn(a, b);
    return *reinterpret_cast<uint32_t*>(&h);
}
static __device__ __forceinline__ __half2 u2h2(uint32_t u){
    return *reinterpret_cast<__half2*>(&u);
}
static __device__ __forceinline__ uint32_t h2u2(__half2 h){
    return *reinterpret_cast<uint32_t*>(&h);
}

#define SCLQ 0.18033688011112042f   // 0.125 * log2(e), folded into Q at QKV epilogue

// -------------------- fused weight convert + ln1 (one launch) --------------------
__global__ __launch_bounds__(256) void prep_all(
    const float* __restrict__ w0, h16* __restrict__ o0,
    const float* __restrict__ w1, h16* __restrict__ o1,
    const float* __restrict__ w2, h16* __restrict__ o2,
    const float* __restrict__ w3, h16* __restrict__ o3,
    const float* __restrict__ x,  const float* __restrict__ lw,
    const float* __restrict__ lb, h16* __restrict__ y)
{
    __shared__ float red[256];
    int tid = threadIdx.x;
    if (blockIdx.x < 6912) {
        int i = blockIdx.x * 256 + tid;
        const float* w; h16* o; int j;
        if (i < 442368)       { w = w0; o = o0; j = i; }
        else if (i < 589824)  { w = w1; o = o1; j = i - 442368; }
        else if (i < 1179648) { w = w2; o = o2; j = i - 589824; }
        else                  { w = w3; o = o3; j = i - 1179648; }
        float4 v = reinterpret_cast<const float4*>(w)[j];
        uint2 r;
        r.x = packf2(v.x, v.y);
        r.y = packf2(v.z, v.w);
        reinterpret_cast<uint2*>(o)[j] = r;
        return;
    }
    int row = blockIdx.x - 6912;
    const float* xr = x + (size_t)row * DD;
    h16* yr = y + (size_t)row * DD;
    float v0 = xr[tid], v1 = xr[tid + 256], v2 = xr[tid + 512];
    red[tid] = v0 + v1 + v2;
    __syncthreads();
    for (int off = 128; off; off >>= 1) {
        if (tid < off) red[tid] += red[tid + off];
        __syncthreads();
    }
    float mean = red[0] * (1.0f / DD);
    __syncthreads();
    float d0 = v0 - mean, d1 = v1 - mean, d2 = v2 - mean;
    red[tid] = d0*d0 + d1*d1 + d2*d2;
    __syncthreads();
    for (int off = 128; off; off >>= 1) {
        if (tid < off) red[tid] += red[tid + off];
        __syncthreads();
    }
    float rstd = rsqrtf(red[0] * (1.0f / DD) + 1e-5f);
    yr[tid]       = __float2half_rn(d0 * rstd * lw[tid]       + lb[tid]);
    yr[tid + 256] = __float2half_rn(d1 * rstd * lw[tid + 256] + lb[tid + 256]);
    yr[tid + 512] = __float2half_rn(d2 * rstd * lw[tid + 512] + lb[tid + 512]);
}

// -------------------- layernorm -> fp16 (ln2) --------------------
__global__ __launch_bounds__(256) void ln_h(const float* __restrict__ x,
                                            const float* __restrict__ w,
                                            const float* __restrict__ b,
                                            h16* __restrict__ y)
{
    __shared__ float red[256];
    int tid = threadIdx.x;
    const float* xr = x + (size_t)blockIdx.x * DD;
    h16* yr = y + (size_t)blockIdx.x * DD;
    float v0 = xr[tid], v1 = xr[tid + 256], v2 = xr[tid + 512];
    red[tid] = v0 + v1 + v2;
    __syncthreads();
    for (int off = 128; off; off >>= 1) {
        if (tid < off) red[tid] += red[tid + off];
        __syncthreads();
    }
    float mean = red[0] * (1.0f / DD);
    __syncthreads();
    float d0 = v0 - mean, d1 = v1 - mean, d2 = v2 - mean;
    red[tid] = d0*d0 + d1*d1 + d2*d2;
    __syncthreads();
    for (int off = 128; off; off >>= 1) {
        if (tid < off) red[tid] += red[tid + off];
        __syncthreads();
    }
    float rstd = rsqrtf(red[0] * (1.0f / DD) + 1e-5f);
    yr[tid]       = __float2half_rn(d0 * rstd * w[tid]       + b[tid]);
    yr[tid + 256] = __float2half_rn(d1 * rstd * w[tid + 256] + b[tid + 256]);
    yr[tid + 512] = __float2half_rn(d2 * rstd * w[tid + 512] + b[tid + 512]);
}

// -------------------- flash attention (fp16, causal, K+V dbl-buffered) ----------
__global__ __launch_bounds__(256) void flash_attn(
    const h16* __restrict__ qkv,
    h16* __restrict__ os)
{
    constexpr int STR = 144;
    constexpr int PL  = 128 * STR;       // 18432 per plane
    extern __shared__ __align__(128) char smem[];

    const int qt = gridDim.x - 1 - blockIdx.x;   // longest jobs first
    const int bh = blockIdx.y;
    const int b = bh / HH, h = bh % HH;
    const int tid = threadIdx.x, wid = tid >> 5, lane = tid & 31;
    const uint32_t sb = smem_u32(smem);

    const h16* Qb = qkv + (size_t)(b * SS + qt * 128) * (3 * DD) + h * HDD;
    const h16* Kb = qkv + (size_t)(b * SS) * (3 * DD) + DD + h * HDD;
    const h16* Vb = Kb + DD;

    auto loadQ = [&]() {
#pragma unroll
        for (int it = 0; it < 4; it++) {
            int idx = tid + it * 256;
            int r = idx >> 3, c = idx & 7;
            CP_ASYNC16(sb + r * STR + c * 16,
                       Qb + (size_t)r * (3 * DD) + c * 8);
        }
        CP_COMMIT();
    };
    auto loadKV = [&](int j, int vb) {
#pragma unroll
        for (int it = 0; it < 4; it++) {
            int idx = tid + it * 256;
            int r = idx >> 3, c = idx & 7;
            CP_ASYNC16(sb + (1 + vb) * PL + r * STR + c * 16,
                       Kb + (size_t)(j * 128 + r) * (3 * DD) + c * 8);
        }
#pragma unroll
        for (int it = 0; it < 4; it++) {
            int idx = tid + it * 256;
            int r = idx >> 3, c = idx & 7;
            CP_ASYNC16(sb + (3 + vb) * PL + r * STR + c * 16,
                       Vb + (size_t)(j * 128 + r) * (3 * DD) + c * 8);
        }
        CP_COMMIT();
    };

    loadQ();
    loadKV(0, 0);

    float mo0 = -1e30f, mo1 = -1e30f;
    float l0 = 0.f, l1 = 0.f;
    float oacc[8][4];
#pragma unroll
    for (int f = 0; f < 8; f++)
#pragma unroll
        for (int c = 0; c < 4; c++) oacc[f][c] = 0.f;

    for (int j = 0; j <= qt; j++) {
        const int vb = j & 1;
        CP_WAIT0();
        __syncthreads();

        // ---- S = Q K^T ----
        float sacc[16][4];
#pragma unroll
        for (int f = 0; f < 16; f++)
#pragma unroll
            for (int c = 0; c < 4; c++) sacc[f][c] = 0.f;

#pragma unroll
        for (int ks = 0; ks < 4; ks++) {
            uint32_t aQ[4];
            uint32_t qaddr = sb + (wid * 16 + (lane & 15)) * STR + ks * 32 + ((lane >> 4) << 4);
            ldsm_x4(aQ, qaddr);
#pragma unroll
            for (int h8 = 0; h8 < 8; h8++) {
                uint32_t row = h8 * 16 + (lane & 7) + ((lane >> 4) << 3);
                uint32_t ch  = (lane >> 3) & 1;
                uint32_t ka  = sb + (1 + vb) * PL + row * STR + ks * 32 + ch * 16;
                uint32_t bK[4];
                ldsm_x4(bK, ka);
                mma16816(sacc[2*h8],   aQ, bK);
                mma16816(sacc[2*h8+1], aQ, bK + 2);
            }
        }

        // ---- online softmax (log2 domain) ----
        const bool diag = (j == qt);
        int rl0 = wid * 16 + (lane >> 2), rl1 = rl0 + 8;
        float mn0 = mo0, mn1 = mo1;
#pragma unroll
        for (int f = 0; f < 16; f++) {
            int cl = f * 8 + (lane & 3) * 2;
            float t0 = sacc[f][0], t1 = sacc[f][1];
            float t2 = sacc[f][2], t3 = sacc[f][3];
            if (diag) {
                if (cl     > rl0) t0 = -1e30f;
                if (cl + 1 > rl0) t1 = -1e30f;
                if (cl     > rl1) t2 = -1e30f;
                if (cl + 1 > rl1) t3 = -1e30f;
            }
            sacc[f][0] = t0; sacc[f][1] = t1; sacc[f][2] = t2; sacc[f][3] = t3;
            mn0 = fmaxf(mn0, fmaxf(t0, t1));
            mn1 = fmaxf(mn1, fmaxf(t2, t3));
        }
        mn0 = fmaxf(mn0, __shfl_xor_sync(0xffffffffu, mn0, 1));
        mn0 = fmaxf(mn0, __shfl_xor_sync(0xffffffffu, mn0, 2));
        mn1 = fmaxf(mn1, __shfl_xor_sync(0xffffffffu, mn1, 1));
        mn1 = fmaxf(mn1, __shfl_xor_sync(0xffffffffu, mn1, 2));

        float f0 = exp2f(mo0 - mn0), f1 = exp2f(mo1 - mn1);
        l0 *= f0; l1 *= f1;
#pragma unroll
        for (int f = 0; f < 8; f++) {
            oacc[f][0] *= f0; oacc[f][1] *= f0;
            oacc[f][2] *= f1; oacc[f][3] *= f1;
        }
        uint32_t pr0[16], pr1[16];
#pragma unroll
        for (int f = 0; f < 16; f++) {
            __half2 ha = __floats2half2_rn(sacc[f][0] - mn0, sacc[f][1] - mn0);
            __half2 hb = __floats2half2_rn(sacc[f][2] - mn1, sacc[f][3] - mn1);
            pr0[f] = h2u2(h2exp2(ha));
            pr1[f] = h2u2(h2exp2(hb));
        }
        float s0 = 0.f, s1 = 0.f;
#pragma unroll
        for (int i = 0; i < 8; i++) {
            __half2 qa = __hadd2(u2h2(pr0[2*i]), u2h2(pr0[2*i+1]));
            __half2 qb = __hadd2(u2h2(pr1[2*i]), u2h2(pr1[2*i+1]));
            s0 += __low2float(qa) + __high2float(qa);
            s1 += __low2float(qb) + __high2float(qb);
        }
        s0 += __shfl_xor_sync(0xffffffffu, s0, 1);
        s0 += __shfl_xor_sync(0xffffffffu, s0, 2);
        s1 += __shfl_xor_sync(0xffffffffu, s1, 1);
        s1 += __shfl_xor_sync(0xffffffffu, s1, 2);
        l0 += s0; l1 += s1;
        mo0 = mn0; mo1 = mn1;

        if (j < qt) loadKV(j + 1, vb ^ 1);

        // ---- O += P V_j ----
#pragma unroll
        for (int kk = 0; kk < 8; kk++) {
            uint32_t aP[4] = { pr0[2*kk], pr1[2*kk], pr0[2*kk+1], pr1[2*kk+1] };
#pragma unroll
            for (int h4 = 0; h4 < 4; h4++) {
                uint32_t row = kk * 16 + (lane & 7) + (((lane >> 3) & 1) << 3);
                uint32_t col = h4 * 16 + ((lane >> 4) << 3);
                uint32_t va  = sb + (3 + vb) * PL + row * STR + col * 2;
                uint32_t bV[4];
                ldsm_x4t(bV, va);
                mma16816(oacc[2*h4],   aP, bV);
                mma16816(oacc[2*h4+1], aP, bV + 2);
            }
        }
    }

    float li0 = 1.0f / l0, li1 = 1.0f / l1;
    int m0r = b * SS + qt * 128 + wid * 16 + (lane >> 2);
    h16* oh = os + (size_t)m0r * DD + h * HDD;
#pragma unroll
    for (int f = 0; f < 8; f++) {
        int n = f * 8 + (lane & 3) * 2;
        *reinterpret_cast<uint32_t*>(oh + n) =
            packf2(oacc[f][0] * li0, oacc[f][1] * li0);
        *reinterpret_cast<uint32_t*>(oh + 8 * DD + n) =
            packf2(oacc[f][2] * li1, oacc[f][3] * li1);
    }
}

// -------------------- fp16 warp-MMA GEMM, BK=64, 3-stage cp.async -------------
// One __syncthreads per k-tile. Preload 2 tiles; steady-state wait_group 1
// gives each load ~2 compute-tiles of latency cover. Final iteration drains.
enum { EPI_QKV = 0, EPI_BIASRES = 1, EPI_GELU = 2 };

template<int BN, int STAGES, int EPI, bool OUT_HALF>
__global__ __launch_bounds__(256, 2) void mma_gemm2(
    const h16* __restrict__ A, const h16* __restrict__ Bm,
    const float* __restrict__ bias, const float* __restrict__ resid,
    void* __restrict__ Cout,
    int K, int lda, int ldb, int ldc)
{
    constexpr int BM = 128, BK = 64;
    constexpr int ASTR = 144;
    constexpr int APL  = BM * ASTR;      // 18432
    constexpr int BSTR = 144;
    constexpr int BPL  = BN * BSTR;      // 18432 / 9216
    constexpr int BUF  = APL + BPL;
    constexpr int MF = (BN == 128) ? 4 : 2;
    constexpr int NF = 4;

    extern __shared__ __align__(128) char smem[];

    const int m0 = blockIdx.y * BM, n0 = blockIdx.x * BN;
    const int tid = threadIdx.x, wid = tid >> 5, lane = tid & 31;
    const int wm0 = (BN == 128) ? (wid & 1) * 64 : (wid & 3) * 32;
    const int wn0 = (BN == 128) ? (wid >> 1) * 32 : (wid >> 2) * 32;
    const uint32_t sb = smem_u32(smem);

    float acc[MF][NF][4];
#pragma unroll
    for (int i = 0; i < MF; i++)
#pragma unroll
        for (int jj = 0; jj < NF; jj++)
#pragma unroll
            for (int c = 0; c < 4; c++) acc[i][jj][c] = 0.f;

    int NT = K / BK;

    auto load_tile = [&](int kt, int bsel) {
        uint32_t base = sb + bsel * BUF;
#pragma unroll
        for (int it = 0; it < 4; it++) {
            int idx = tid + it * 256;
            int r = idx >> 3, c = idx & 7;
            const h16* src = A + (size_t)(m0 + r) * lda + kt * BK + c * 8;
            CP_ASYNC16(base + r * ASTR + c * 16, src);
        }
#pragma unroll
        for (int it = 0; it < BN / 32; it++) {
            int idx = tid + it * 256;
            int r = idx >> 3, c = idx & 7;
            const h16* src = Bm + (size_t)(n0 + r) * ldb + kt * BK + c * 8;
            CP_ASYNC16(base + APL + r * BSTR + c * 16, src);
        }
        CP_COMMIT();
    };

    load_tile(0, 0);
    if (STAGES == 3 && NT > 1) load_tile(1, 1);

    for (int kt = 0; kt < NT; kt++) {
        int buf = kt % STAGES;
        if (STAGES == 3 && kt + 1 < NT) CP_WAIT1();
        else                            CP_WAIT0();
        __syncthreads();
        int nx = kt + STAGES - 1;
        if (nx < NT) load_tile(nx, nx % STAGES);

        uint32_t base = sb + buf * BUF;
#pragma unroll
        for (int ks = 0; ks < 4; ks++) {
            uint32_t bB[NF][2];
#pragma unroll
            for (int hh = 0; hh < 2; hh++) {
                uint32_t row = wn0 + hh * 16 + (lane & 7) + ((lane >> 4) << 3);
                uint32_t ch  = (lane >> 3) & 1;
                uint32_t ad  = base + APL + row * BSTR + ks * 32 + ch * 16;
                uint32_t r4[4];
                ldsm_x4(r4, ad);
                bB[hh*2][0]=r4[0]; bB[hh*2][1]=r4[1]; bB[hh*2+1][0]=r4[2]; bB[hh*2+1][1]=r4[3];
            }
#pragma unroll
            for (int mf = 0; mf < MF; mf++) {
                uint32_t row = wm0 + mf * 16 + (lane & 15);
                uint32_t ch  = lane >> 4;
                uint32_t ad  = base + row * ASTR + ks * 32 + ch * 16;
                uint32_t aA[4];
                ldsm_x4(aA, ad);
#pragma unroll
                for (int nf = 0; nf < NF; nf++)
                    mma16816(acc[mf][nf], aA, bB[nf]);
            }
        }
        // no trailing sync — next iteration's top sync covers buffer reuse
    }

    // -------- epilogue --------
#pragma unroll
    for (int mf = 0; mf < MF; mf++) {
#pragma unroll
        for (int half = 0; half < 2; half++) {
            int m = m0 + wm0 + mf * 16 + (lane >> 2) + half * 8;
#pragma unroll
            for (int nf = 0; nf < NF; nf++) {
                int n = n0 + wn0 + nf * 8 + (lane & 3) * 2;
                float v0 = acc[mf][nf][half*2 + 0];
                float v1 = acc[mf][nf][half*2 + 1];
                if (bias) { v0 += __ldg(&bias[n]); v1 += __ldg(&bias[n+1]); }
                if (EPI == EPI_QKV) {
                    if (n < DD)     v0 *= SCLQ;
                    if (n + 1 < DD) v1 *= SCLQ;
                }
                if (EPI == EPI_GELU) {
                    v0 = 0.5f * v0 * (1.0f + erff(v0 * 0.70710678118654752f));
                    v1 = 0.5f * v1 * (1.0f + erff(v1 * 0.70710678118654752f));
                }
                if (EPI == EPI_BIASRES) {
                    const float* Rrow = resid + (size_t)m * ldc;
                    v0 += Rrow[n]; v1 += Rrow[n+1];
                }
                if (OUT_HALF) {
                    h16* Ch = (h16*)Cout + (size_t)m * ldc;
                    *reinterpret_cast<uint32_t*>(Ch + n) = packf2(v0, v1);
                } else {
                    float* Crow = (float*)Cout + (size_t)m * ldc;
                    *reinterpret_cast<float2*>(Crow + n) = make_float2(v0, v1);
                }
            }
        }
    }
}

// -------------------- host launcher --------------------
extern "C" void kernel_launch(void* const* d_in, const int* in_sizes, int n_in,
                              void* d_out, int out_size)
{
    const float* x     = (const float*)d_in[0];
    const float* qkv_w = (const float*)d_in[2];
    const float* qkv_b = (const float*)d_in[3];
    const float* out_w = (const float*)d_in[4];
    const float* out_b = (const float*)d_in[5];
    const float* fc1_w = (const float*)d_in[6];
    const float* fc1_b = (const float*)d_in[7];
    const float* fc2_w = (const float*)d_in[8];
    const float* fc2_b = (const float*)d_in[9];
    const float* ln1_w = (const float*)d_in[10];
    const float* ln1_b = (const float*)d_in[11];
    const float* ln2_w = (const float*)d_in[12];
    const float* ln2_b = (const float*)d_in[13];
    float* out = (float*)d_out;

    void *p0,*p1,*p4,*p5,*p6,*p7,*p8,*p9,*p10,*p11;
    cudaGetSymbolAddress(&p0,  g_hx);
    cudaGetSymbolAddress(&p1,  g_qkv);
    cudaGetSymbolAddress(&p4,  g_o);
    cudaGetSymbolAddress(&p5,  g_x1);
    cudaGetSymbolAddress(&p6,  g_h2);
    cudaGetSymbolAddress(&p7,  g_ff1);
    cudaGetSymbolAddress(&p8,  g_qkvw);
    cudaGetSymbolAddress(&p9,  g_outw);
    cudaGetSymbolAddress(&p10, g_fc1w);
    cudaGetSymbolAddress(&p11, g_fc2w);
    h16* hx   = (h16*)p0;  h16* qkv  = (h16*)p1;
    h16* o    = (h16*)p4;  float* x1 = (float*)p5;
    h16* h2   = (h16*)p6;  h16* ff1  = (h16*)p7;
    h16* qkvw = (h16*)p8;  h16* outw = (h16*)p9;
    h16* fc1w = (h16*)p10; h16* fc2w = (h16*)p11;

    const int SMEM_G128_3 = 3 * (18432 + 18432);  // 110592 (3-stage BN=128)
    const int SMEM_G64_3  = 3 * (18432 + 9216);   // 82944  (3-stage BN=64)
    const int SMEM_FA     = 5 * 128 * 144;        // 92160

    cudaFuncSetAttribute(mma_gemm2<128,3,EPI_QKV,    true >,
                         cudaFuncAttributeMaxDynamicSharedMemorySize, SMEM_G128_3);
    cudaFuncSetAttribute(mma_gemm2<64, 3,EPI_BIASRES,false>,
                         cudaFuncAttributeMaxDynamicSharedMemorySize, SMEM_G64_3);
    cudaFuncSetAttribute(mma_gemm2<128,3,EPI_GELU,   true >,
                         cudaFuncAttributeMaxDynamicSharedMemorySize, SMEM_G128_3);
    cudaFuncSetAttribute(flash_attn,
                         cudaFuncAttributeMaxDynamicSharedMemorySize, SMEM_FA);

    // 0+1. weight converts + ln1 fused
    prep_all<<<6912 + ROWS, 256>>>(qkv_w, qkvw, out_w, outw,
                                   fc1_w, fc1w, fc2_w, fc2w,
                                   x, ln1_w, ln1_b, hx);

    // 2. QKV (Q pre-scaled in epilogue) — BN=128, 3-stage
    mma_gemm2<128,3,EPI_QKV,true>
        <<<dim3(3*DD/128, ROWS/128, 1), 256, SMEM_G128_3>>>(
            hx, qkvw, qkv_b, nullptr, qkv,
            DD, DD, DD, 3*DD);

    // 3-5. flash attention -> o fp16
    flash_attn<<<dim3(SS/128, BH), 256, SMEM_FA>>>(qkv, o);

    // 6. x1 = x + O @ out_w^T + out_b   (fp32 out; BN=64, 3-stage)
    mma_gemm2<64,3,EPI_BIASRES,false>
        <<<dim3(DD/64, ROWS/128, 1), 256, SMEM_G64_3>>>(
            o, outw, out_b, x, x1,
            DD, DD, DD, DD);

    // 7. ln2 -> h2 fp16
    ln_h<<<ROWS, 256>>>(x1, ln2_w, ln2_b, h2);

    // 8. ff1 = gelu(h2 @ fc1_w^T + fc1_b) -> fp16  (BN=128, 3-stage)
    mma_gemm2<128,3,EPI_GELU,true>
        <<<dim3(FF/128, ROWS/128, 1), 256, SMEM_G128_3>>>(
            h2, fc1w, fc1_b, nullptr, ff1,
            DD, DD, DD, FF);

    // 9. out = x1 + ff1 @ fc2_w^T + fc2_b   (fp32 out; BN=64, 3-stage)
    mma_gemm2<64,3,EPI_BIASRES,false>
        <<<dim3(DD/64, ROWS/128, 1), 256, SMEM_G64_3>>>(
            ff1, fc2w, fc2_b, x1, out,
            FF, FF, FF, DD);
}